// round 16
// baseline (speedup 1.0000x reference)
#include <cuda_runtime.h>
#include <cuda_fp16.h>
#include <cstdint>

#define NB 4
#define SL 2048
#define EQ 512
#define ET 512
#define NH 8
#define EH 64
#define NF 8

typedef __half fp16;

#define QSCALE 0.18033688f      // (1/8)*log2(e)
#define EXP2_OFF 5.7707802f     // 4*log2(e)
#define ONESH2 0x3C003C00u      // half2(1.0, 1.0)

// ---------------- scratch (device globals; no allocation allowed) ----------------
__device__ __align__(16) fp16 g_wh   [EQ * 3 * ET];
__device__ __align__(16) fp16 g_qkvh [NB * SL * 3 * ET];
__device__ __align__(16) fp16 g_oh   [NB * SL * ET];
__device__ __align__(16) fp16 g_weffh[NF * ET * EQ];

// ---------------- PTX helpers ----------------
__device__ __forceinline__ uint32_t sptr(const void* p) {
    return (uint32_t)__cvta_generic_to_shared(p);
}
__device__ __forceinline__ void cpasync16(uint32_t s, const void* g) {
    asm volatile("cp.async.cg.shared.global [%0], [%1], 16;\n" :: "r"(s), "l"(g));
}
__device__ __forceinline__ void cpcommit() {
    asm volatile("cp.async.commit_group;\n");
}
template<int N> __device__ __forceinline__ void cpwait() {
    asm volatile("cp.async.wait_group %0;\n" :: "n"(N));
}
__device__ __forceinline__ void ldsm4(uint32_t* r, uint32_t a) {
    asm volatile("ldmatrix.sync.aligned.m8n8.x4.shared.b16 {%0,%1,%2,%3},[%4];\n"
                 : "=r"(r[0]), "=r"(r[1]), "=r"(r[2]), "=r"(r[3]) : "r"(a));
}
__device__ __forceinline__ void ldsm4t(uint32_t* r, uint32_t a) {
    asm volatile("ldmatrix.sync.aligned.m8n8.x4.trans.shared.b16 {%0,%1,%2,%3},[%4];\n"
                 : "=r"(r[0]), "=r"(r[1]), "=r"(r[2]), "=r"(r[3]) : "r"(a));
}
__device__ __forceinline__ void mmah(float* c, const uint32_t* a, uint32_t b0, uint32_t b1) {
    asm volatile("mma.sync.aligned.m16n8k16.row.col.f32.f16.f16.f32 "
                 "{%0,%1,%2,%3},{%4,%5,%6,%7},{%8,%9},{%0,%1,%2,%3};\n"
                 : "+f"(c[0]), "+f"(c[1]), "+f"(c[2]), "+f"(c[3])
                 : "r"(a[0]), "r"(a[1]), "r"(a[2]), "r"(a[3]), "r"(b0), "r"(b1));
}
__device__ __forceinline__ uint32_t cvt2h(float hi, float lo) {
    uint32_t d;
    asm("cvt.rn.f16x2.f32 %0, %1, %2;" : "=r"(d) : "f"(hi), "f"(lo));
    return d;
}
__device__ __forceinline__ uint32_t ex2h2(uint32_t x) {
    uint32_t d;
    asm("ex2.approx.f16x2 %0, %1;" : "=r"(d) : "r"(x));
    return d;
}
__device__ __forceinline__ void sts4(uint32_t a, uint32_t r0, uint32_t r1,
                                     uint32_t r2, uint32_t r3) {
    asm volatile("st.shared.v4.b32 [%0], {%1,%2,%3,%4};\n"
                 :: "r"(a), "r"(r0), "r"(r1), "r"(r2), "r"(r3) : "memory");
}

// ---------------- split: Wqkv -> fp16 (query handled inside gemm1f) ----------------
#define NW4 (EQ * 3 * ET / 4)

__global__ void __launch_bounds__(256)
splitw_kernel(const float* __restrict__ Wqkv, fp16* __restrict__ wh)
{
    int j = blockIdx.x * 256 + threadIdx.x;
    if (j >= NW4) return;
    float4 v = ((const float4*)Wqkv)[j];
    ((__half2*)wh)[2 * j]     = __halves2half2(__float2half_rn(v.x), __float2half_rn(v.y));
    ((__half2*)wh)[2 * j + 1] = __halves2half2(__float2half_rn(v.z), __float2half_rn(v.w));
}

// ---------------- gemm1 with fused fp32->fp16 A conversion --------------------------
// qkv = query(fp32)·Wqkv(fp16) + bqkv -> fp16, q cols scaled by QSCALE.
// M=8192, N=1536, K=512; 128x128 tiles, BK=64, 2 smem stages.
#define G1_BHO 9216
#define G1_GS  17920

__global__ void __launch_bounds__(256, 2)
gemm1f(const float* __restrict__ A, const fp16* __restrict__ B,
       const float* __restrict__ bias, fp16* __restrict__ Ch)
{
    extern __shared__ fp16 sm[];
    int tid = threadIdx.x, lane = tid & 31, wid = tid >> 5;
    int wm = wid >> 2, wn = wid & 3;
    int m0 = blockIdx.y * 128, n0c = blockIdx.x * 128;
    uint32_t sbase = sptr(sm);

    int chunk = tid & 7, rowa = tid >> 3;
    int ckb = tid & 15, rowb = tid >> 4;

    const float* aP = A + (size_t)(m0 + rowa) * 512 + chunk * 8;
    const fp16* bP = B + (size_t)rowb * 1536 + n0c + ckb * 8;
    uint32_t sAo = (uint32_t)(rowa * 72 + chunk * 8) * 2;
    uint32_t sBo = (uint32_t)(G1_BHO + rowb * 136 + ckb * 8) * 2;

    uint2 pa[8];
    auto ldgA = [&](int kt) {
        const float* p = aP + kt * 64;
#pragma unroll
        for (int rep = 0; rep < 4; rep++) {
            float4 v0 = *(const float4*)(p + rep * (32 * 512));
            float4 v1 = *(const float4*)(p + rep * (32 * 512) + 4);
            pa[2 * rep]     = make_uint2(cvt2h(v0.y, v0.x), cvt2h(v0.w, v0.z));
            pa[2 * rep + 1] = make_uint2(cvt2h(v1.y, v1.x), cvt2h(v1.w, v1.z));
        }
    };
    auto stsA = [&](int buf) {
        uint32_t sb = sbase + buf * G1_GS * 2 + sAo;
#pragma unroll
        for (int rep = 0; rep < 4; rep++)
            sts4(sb + rep * (32 * 72 * 2),
                 pa[2 * rep].x, pa[2 * rep].y, pa[2 * rep + 1].x, pa[2 * rep + 1].y);
    };
    auto ldB = [&](int kt, int buf) {
        uint32_t sb = sbase + buf * G1_GS * 2;
        const fp16* p = bP + (size_t)kt * 64 * 1536;
#pragma unroll
        for (int rep = 0; rep < 4; rep++)
            cpasync16(sb + sBo + rep * (16 * 136 * 2), p + (size_t)rep * 16 * 1536);
        cpcommit();
    };

    float acc[4][4][4];
#pragma unroll
    for (int i = 0; i < 4; i++)
#pragma unroll
        for (int j = 0; j < 4; j++)
#pragma unroll
            for (int k = 0; k < 4; k++) acc[i][j][k] = 0.f;

    int arow = wm * 64 + (lane & 15);
    int acolsel = (lane >> 4) << 3;
    int krow = (lane & 7) + ((lane >> 4) << 3);
    int bcolw = wn * 32 + ((lane >> 3) & 1) * 8;
    uint32_t aoff = (uint32_t)(arow * 72 + acolsel) * 2;
    uint32_t boff = (uint32_t)(G1_BHO + krow * 136 + bcolw) * 2;

    ldgA(0);
    ldB(0, 0);
    for (int kt = 0; kt < 8; kt++) {
        if (kt > 0) __syncthreads();           // prev mma done reading both bufs
        if (kt < 7) ldB(kt + 1, (kt + 1) & 1);
        stsA(kt & 1);
        if (kt < 7) ldgA(kt + 1);
        if (kt < 7) cpwait<1>(); else cpwait<0>();
        __syncthreads();

        uint32_t aB0 = sbase + (kt & 1) * G1_GS * 2 + aoff;
        uint32_t bB0 = sbase + (kt & 1) * G1_GS * 2 + boff;
        uint32_t bcur[2][4];
        ldsm4t(bcur[0], bB0);
        ldsm4t(bcur[1], bB0 + 32);
#pragma unroll
        for (int ks = 0; ks < 4; ks++) {
            uint32_t ah[4][4];
#pragma unroll
            for (int mi = 0; mi < 4; mi++)
                ldsm4(ah[mi], aB0 + ks * 32 + mi * (16 * 72 * 2));
            uint32_t bnxt[2][4];
            if (ks < 3) {
                ldsm4t(bnxt[0], bB0 + (ks + 1) * (16 * 136 * 2));
                ldsm4t(bnxt[1], bB0 + (ks + 1) * (16 * 136 * 2) + 32);
            }
#pragma unroll
            for (int mi = 0; mi < 4; mi++)
#pragma unroll
                for (int nf = 0; nf < 4; nf++) {
                    int g = nf >> 1, s = nf & 1;
                    mmah(acc[mi][nf], ah[mi], bcur[g][s], bcur[g][s + 2]);
                }
            if (ks < 3) {
#pragma unroll
                for (int g = 0; g < 2; g++)
#pragma unroll
                    for (int s = 0; s < 4; s++) bcur[g][s] = bnxt[g][s];
            }
        }
    }

#pragma unroll
    for (int mi = 0; mi < 4; mi++)
#pragma unroll
        for (int nf = 0; nf < 4; nf++) {
            int r = m0 + wm * 64 + mi * 16 + (lane >> 2);
            int c = n0c + wn * 32 + nf * 8 + (lane & 3) * 2;
            float b0 = bias[c], b1 = bias[c + 1];
            float v00 = acc[mi][nf][0] + b0, v01 = acc[mi][nf][1] + b1;
            float v10 = acc[mi][nf][2] + b0, v11 = acc[mi][nf][3] + b1;
            if (c < EQ) { v00 *= QSCALE; v01 *= QSCALE; v10 *= QSCALE; v11 *= QSCALE; }
            size_t i0 = (size_t)r * 1536 + c;
            size_t i1 = i0 + (size_t)8 * 1536;
            *(__half2*)(Ch + i0) = __halves2half2(__float2half_rn(v00), __float2half_rn(v01));
            *(__half2*)(Ch + i1) = __halves2half2(__float2half_rn(v10), __float2half_rn(v11));
        }
}

// ---------------- fp16 tensor-core GEMM (gemm2), 128x128 tiles, BK=64 ---------------
__global__ void __launch_bounds__(256)
mma_gemm(const fp16* __restrict__ Ah_, const fp16* __restrict__ Bh_,
         const float* __restrict__ bias, float* __restrict__ C,
         int M, int N, int K, size_t aB, size_t bB, size_t cB)
{
    constexpr int BHOc = 9216;
    constexpr int GSc  = BHOc + 8704;

    extern __shared__ fp16 sm[];
    int z = blockIdx.z;

    int tid = threadIdx.x, lane = tid & 31, wid = tid >> 5;
    int wm = wid >> 2, wn = wid & 3;
    int m0 = blockIdx.y * 128, n0c = blockIdx.x * 128;
    uint32_t sbase = sptr(sm);

    int chunk = tid & 7, rowa = tid >> 3;
    int ckb = tid & 15, rowb = tid >> 4;

    const fp16* aP = Ah_ + (size_t)(z >> 3) * aB + (size_t)(m0 + rowa) * K + chunk * 8;
    const fp16* bP = Bh_ + (size_t)(z & 7) * bB + (size_t)rowb * N + n0c + ckb * 8;
    const size_t aStep = (size_t)32 * K;
    const size_t bStep = (size_t)16 * N;
    uint32_t sAo = (uint32_t)(rowa * 72 + chunk * 8) * 2;
    uint32_t sBo = (uint32_t)(BHOc + rowb * 136 + ckb * 8) * 2;

    auto loadTile = [&](int buf) {
        uint32_t sb = sbase + buf * GSc * 2;
#pragma unroll
        for (int rep = 0; rep < 4; rep++) {
            cpasync16(sb + sAo + rep * (32 * 72 * 2), aP + rep * aStep);
            cpasync16(sb + sBo + rep * (16 * 136 * 2), bP + rep * bStep);
        }
        cpcommit();
        aP += 64;
        bP += (size_t)64 * N;
    };

    float acc[4][4][4];
#pragma unroll
    for (int i = 0; i < 4; i++)
#pragma unroll
        for (int j = 0; j < 4; j++)
#pragma unroll
            for (int k = 0; k < 4; k++) acc[i][j][k] = 0.f;

    int arow = wm * 64 + (lane & 15);
    int acolsel = (lane >> 4) << 3;
    int krow = (lane & 7) + ((lane >> 4) << 3);
    int bcolw = wn * 32 + ((lane >> 3) & 1) * 8;
    uint32_t aoff = (uint32_t)(arow * 72 + acolsel) * 2;
    uint32_t boff = (uint32_t)(BHOc + krow * 136 + bcolw) * 2;

    int nk = K / 64;
    loadTile(0);
    for (int kt = 0; kt < nk; kt++) {
        if (kt + 1 < nk) { loadTile((kt + 1) & 1); cpwait<1>(); }
        else             { cpwait<0>(); }
        __syncthreads();
        uint32_t aB0 = sbase + (kt & 1) * GSc * 2 + aoff;
        uint32_t bB0 = sbase + (kt & 1) * GSc * 2 + boff;

        uint32_t bcur[2][4];
        ldsm4t(bcur[0], bB0);
        ldsm4t(bcur[1], bB0 + 32);
#pragma unroll
        for (int ks = 0; ks < 4; ks++) {
            uint32_t ah[4][4];
#pragma unroll
            for (int mi = 0; mi < 4; mi++)
                ldsm4(ah[mi], aB0 + ks * 32 + mi * (16 * 72 * 2));
            uint32_t bnxt[2][4];
            if (ks < 3) {
                ldsm4t(bnxt[0], bB0 + (ks + 1) * (16 * 136 * 2));
                ldsm4t(bnxt[1], bB0 + (ks + 1) * (16 * 136 * 2) + 32);
            }
#pragma unroll
            for (int mi = 0; mi < 4; mi++)
#pragma unroll
                for (int nf = 0; nf < 4; nf++) {
                    int g = nf >> 1, s = nf & 1;
                    mmah(acc[mi][nf], ah[mi], bcur[g][s], bcur[g][s + 2]);
                }
            if (ks < 3) {
#pragma unroll
                for (int g = 0; g < 2; g++)
#pragma unroll
                    for (int s = 0; s < 4; s++) bcur[g][s] = bnxt[g][s];
            }
        }
        __syncthreads();
    }

#pragma unroll
    for (int mi = 0; mi < 4; mi++)
#pragma unroll
        for (int nf = 0; nf < 4; nf++) {
            int r = m0 + wm * 64 + mi * 16 + (lane >> 2);
            int c = n0c + wn * 32 + nf * 8 + (lane & 3) * 2;
            float b0 = bias[c], b1 = bias[c + 1];
            float* Cz = C + (size_t)z * cB;
            *(float2*)(Cz + (size_t)r * N + c) =
                make_float2(acc[mi][nf][0] + b0, acc[mi][nf][1] + b1);
            *(float2*)(Cz + (size_t)(r + 8) * N + c) =
                make_float2(acc[mi][nf][2] + b0, acc[mi][nf][3] + b1);
        }
}

// ---------------- powweff device function (runs inside attention launch) ----------
__device__ void powweff_body(float* pw, const float* __restrict__ Xi,
                             const float* __restrict__ Wo, int idx)
{
    float* Mh = pw;
    float* R  = pw + 4352;
    float* RT = pw + 2 * 4352;
    int half = idx & 1;
    int nh = idx >> 1;
    int n = nh >> 3, h = nh & 7;
    int tid = threadIdx.x;
    const float* X = Xi + h * 64 * 64;

#pragma unroll
    for (int t = 0; t < 16; t++) {
        int id2 = tid + t * 256;
        int i = id2 >> 6, j = id2 & 63;
        float v = X[i * 64 + j] - X[j * 64 + i];
        if (i == j) v += 1.f;
        Mh[i * 68 + j] = v;
        R [i * 68 + j] = v;
        RT[j * 68 + i] = v;
    }
    __syncthreads();

    int i0 = (tid >> 4) * 4, j0 = (tid & 15) * 4;
    auto mult = [&](const float* B) {
        float acc[4][4];
#pragma unroll
        for (int a = 0; a < 4; a++)
#pragma unroll
            for (int bq = 0; bq < 4; bq++) acc[a][bq] = 0.f;
#pragma unroll 4
        for (int k = 0; k < 64; k++) {
            float4 av = *(const float4*)&RT[k * 68 + i0];
            float4 bv = *(const float4*)&B[k * 68 + j0];
            float aa[4] = {av.x, av.y, av.z, av.w};
            float bb[4] = {bv.x, bv.y, bv.z, bv.w};
#pragma unroll
            for (int a = 0; a < 4; a++)
#pragma unroll
                for (int bq = 0; bq < 4; bq++)
                    acc[a][bq] = fmaf(aa[a], bb[bq], acc[a][bq]);
        }
        __syncthreads();
#pragma unroll
        for (int a = 0; a < 4; a++)
#pragma unroll
            for (int bq = 0; bq < 4; bq++) {
                R [(i0 + a) * 68 + j0 + bq] = acc[a][bq];
                RT[(j0 + bq) * 68 + i0 + a] = acc[a][bq];
            }
        __syncthreads();
    };

    int e = n + 1;
    if (e > 1) {
        int msb = 31 - __clz(e);
        for (int bpos = msb - 1; bpos >= 0; bpos--) {
            mult(R);
            if ((e >> bpos) & 1) mult(Mh);
        }
    }

    int c = half * 256 + tid;
    const float* WoH = Wo + (size_t)h * 64 * EQ;
    size_t ob = (size_t)n * ET * EQ + (size_t)h * 64 * EQ;
    float acc[4][16];
#pragma unroll
    for (int p = 0; p < 4; p++)
#pragma unroll
        for (int ii = 0; ii < 16; ii++) acc[p][ii] = 0.f;
    for (int j = 0; j < 64; j++) {
        float wv = WoH[j * EQ + c];
        const float* row = &RT[j * 68];
#pragma unroll
        for (int p = 0; p < 4; p++) {
#pragma unroll
            for (int q4 = 0; q4 < 4; q4++) {
                float4 rv = *(const float4*)&row[p * 16 + q4 * 4];
                acc[p][q4 * 4 + 0] = fmaf(rv.x, wv, acc[p][q4 * 4 + 0]);
                acc[p][q4 * 4 + 1] = fmaf(rv.y, wv, acc[p][q4 * 4 + 1]);
                acc[p][q4 * 4 + 2] = fmaf(rv.z, wv, acc[p][q4 * 4 + 2]);
                acc[p][q4 * 4 + 3] = fmaf(rv.w, wv, acc[p][q4 * 4 + 3]);
            }
        }
    }
#pragma unroll
    for (int p = 0; p < 4; p++)
#pragma unroll
        for (int ii = 0; ii < 16; ii++)
            g_weffh[ob + (size_t)(p * 16 + ii) * EQ + c] = __float2half_rn(acc[p][ii]);
}

// ---------------- attention + powweff, one launch ----------------
#define ASTR 72
#define QH_OFF 0
#define KV_OFF 9216
#define KVSTAGE 9216
#define ATTN_SMEM ((9216 + 3 * 9216) * 2)
#define PW_BLOCKS (2 * NF * NH)

__global__ void __launch_bounds__(256, 2)
attn_pow_kernel(const float* __restrict__ Xi, const float* __restrict__ Wo)
{
    extern __shared__ fp16 smb[];
    if (blockIdx.x < PW_BLOCKS) {
        powweff_body((float*)smb, Xi, Wo, blockIdx.x);
        return;
    }
    int ab = blockIdx.x - PW_BLOCKS;
    int qt = 15 - (ab & 15);
    int bh = ab >> 4;
    int b = bh >> 3, h = bh & 7;
    int tid = threadIdx.x, lane = tid & 31, w = tid >> 5;
    int q0 = qt * 128;
    int hoff = h * EH;
    const fp16* qkvh = g_qkvh + (size_t)b * SL * 1536;

    {
        int chunk = tid & 7;
        int row = tid >> 3;
#pragma unroll
        for (int it = 0; it < 4; it++) {
            int r = row + it * 32;
            cpasync16(sptr(smb + QH_OFF + r * ASTR + chunk * 8),
                      qkvh + (size_t)(q0 + r) * 1536 + hoff + chunk * 8);
        }
    }
    auto loadKV = [&](int kt, int stage) {
        int kv0 = kt * 64;
        fp16* base = smb + KV_OFF + stage * KVSTAGE;
        int chunk = tid & 7;
        int row = tid >> 3;
#pragma unroll
        for (int it = 0; it < 4; it++) {
            int arr = it >> 1;
            int r = row + (it & 1) * 32;
            int colbase = (arr == 0) ? (ET + hoff) : (2 * ET + hoff);
            cpasync16(sptr(base + arr * 4608 + r * ASTR + chunk * 8),
                      qkvh + (size_t)(kv0 + r) * 1536 + colbase + chunk * 8);
        }
        cpcommit();
    };

    int kmax = 2 * qt + 1;
    loadKV(0, 0);
    loadKV(1, 1);

    float lacc[4] = {0.f, 0.f, 0.f, 0.f};
    float oc[8][4];
#pragma unroll
    for (int i = 0; i < 8; i++)
#pragma unroll
        for (int j = 0; j < 4; j++) oc[i][j] = 0.f;

    int arow = w * 16 + (lane & 15);
    int acolsel = (lane >> 4) << 3;
    int krow = (lane & 7) + ((lane >> 4) << 3);
    int kcolsel = ((lane >> 3) & 1) << 3;
    int vrowbase = krow;

    cpwait<1>();
    __syncthreads();

    uint32_t qf[4][4];
#pragma unroll
    for (int kc = 0; kc < 4; kc++)
        ldsm4(qf[kc], sptr(smb + QH_OFF + arow * ASTR + kc * 16 + acolsel));

    for (int kt = 0; kt <= kmax; kt++) {
        if (kt > 0) {
            cpwait<1>();
            __syncthreads();
        }
        if (kt + 2 <= kmax) loadKV(kt + 2, (kt + 2) % 3);
        else                cpcommit();

        fp16* base = smb + KV_OFF + (kt % 3) * KVSTAGE;
        fp16* KH = base;
        fp16* VH = base + 4608;

        float sc[8][4];
#pragma unroll
        for (int i = 0; i < 8; i++)
#pragma unroll
            for (int j = 0; j < 4; j++) sc[i][j] = -EXP2_OFF;

#pragma unroll
        for (int kc = 0; kc < 4; kc++) {
            int kcol = kc * 16 + kcolsel;
#pragma unroll
            for (int g = 0; g < 4; g++) {
                uint32_t b4h[4];
                ldsm4(b4h, sptr(KH + (g * 16 + krow) * ASTR + kcol));
                mmah(sc[2 * g],     qf[kc], b4h[0], b4h[1]);
                mmah(sc[2 * g + 1], qf[kc], b4h[2], b4h[3]);
            }
        }

        if (kt >= 2 * qt) {
            int kv0 = kt * 64;
            int r0 = q0 + w * 16 + (lane >> 2);
#pragma unroll
            for (int nf = 0; nf < 8; nf++) {
                int c0 = kv0 + nf * 8 + (lane & 3) * 2;
                if (c0 > r0)     sc[nf][0] = -1e30f;
                if (c0 + 1 > r0) sc[nf][1] = -1e30f;
                if (c0 > r0 + 8)     sc[nf][2] = -1e30f;
                if (c0 + 1 > r0 + 8) sc[nf][3] = -1e30f;
            }
        }

#pragma unroll
        for (int kc = 0; kc < 4; kc++) {
            uint32_t pah[4];
#pragma unroll
            for (int half = 0; half < 2; half++) {
                int nf = 2 * kc + half;
                pah[half * 2 + 0] = ex2h2(cvt2h(sc[nf][1], sc[nf][0]));
                pah[half * 2 + 1] = ex2h2(cvt2h(sc[nf][3], sc[nf][2]));
            }
            mmah(lacc, pah, ONESH2, ONESH2);
            int vrow = kc * 16 + vrowbase;
#pragma unroll
            for (int g = 0; g < 4; g++) {
                int vcol = g * 16 + kcolsel;
                uint32_t v4h[4];
                ldsm4t(v4h, sptr(VH + vrow * ASTR + vcol));
                mmah(oc[2 * g],     pah, v4h[0], v4h[2]);
                mmah(oc[2 * g + 1], pah, v4h[1], v4h[3]);
            }
        }
    }

    float inv0 = 1.f / lacc[0], inv1 = 1.f / lacc[2];
    int row0 = q0 + w * 16 + (lane >> 2);
    size_t ob = (size_t)b * SL * ET;
#pragma unroll
    for (int nf = 0; nf < 8; nf++) {
        int col = hoff + nf * 8 + (lane & 3) * 2;
        size_t i0 = ob + (size_t)row0 * ET + col;
        size_t i1 = ob + (size_t)(row0 + 8) * ET + col;
        *(__half2*)(g_oh + i0) = __halves2half2(
            __float2half_rn(oc[nf][0] * inv0), __float2half_rn(oc[nf][1] * inv0));
        *(__half2*)(g_oh + i1) = __halves2half2(
            __float2half_rn(oc[nf][2] * inv1), __float2half_rn(oc[nf][3] * inv1));
    }
}

// ---------------- launch ----------------
extern "C" void kernel_launch(void* const* d_in, const int* in_sizes, int n_in,
                              void* d_out, int out_size)
{
    const float* query = (const float*)d_in[0];
    const float* Wqkv  = (const float*)d_in[3];
    const float* bqkv  = (const float*)d_in[4];
    const float* Wo    = (const float*)d_in[5];
    const float* bo    = (const float*)d_in[6];
    const float* Xi    = (const float*)d_in[7];
    float* out = (float*)d_out;

    fp16 *wh, *qkvh, *oh, *weh;
    cudaGetSymbolAddress((void**)&wh, g_wh);
    cudaGetSymbolAddress((void**)&qkvh, g_qkvh);
    cudaGetSymbolAddress((void**)&oh, g_oh);
    cudaGetSymbolAddress((void**)&weh, g_weffh);

    constexpr int SM1 = 2 * 17920 * 2;
    cudaFuncSetAttribute(gemm1f, cudaFuncAttributeMaxDynamicSharedMemorySize, SM1);
    cudaFuncSetAttribute(mma_gemm, cudaFuncAttributeMaxDynamicSharedMemorySize, SM1);
    cudaFuncSetAttribute(attn_pow_kernel, cudaFuncAttributeMaxDynamicSharedMemorySize, ATTN_SMEM);

    // 0) Wqkv -> fp16 (query converted inside gemm1f)
    splitw_kernel<<<(NW4 + 255) / 256, 256>>>(Wqkv, wh);

    // 1) QKV projection (fused fp32-A convert) -> fp16 qkv, q cols scaled
    dim3 g1(3 * ET / 128, NB * SL / 128, 1);
    gemm1f<<<g1, 256, SM1>>>(query, wh, bqkv, qkvh);

    // 2) attention + powweff in one launch
    attn_pow_kernel<<<PW_BLOCKS + 16 * NB * NH, 256, ATTN_SMEM>>>(Xi, Wo);

    // 3) fused forecast+output projection -> fp32 out
    dim3 g2(EQ / 128, SL / 128, NB * NF);
    mma_gemm<<<g2, 256, SM1>>>(oh, weh, bo, out,
                               SL, EQ, ET,
                               (size_t)SL * ET, (size_t)ET * EQ, (size_t)SL * EQ);
}

// round 17
// speedup vs baseline: 1.0236x; 1.0236x over previous
#include <cuda_runtime.h>
#include <cuda_fp16.h>
#include <cstdint>

#define NB 4
#define SL 2048
#define EQ 512
#define ET 512
#define NH 8
#define EH 64
#define NF 8

typedef __half fp16;

// q pre-scale includes log2(e): (1/8)*log2(e); attention uses ex2 in log2 domain
#define QSCALE 0.18033688f
#define EXP2_OFF 5.7707802f     // 4 * log2(e)
#define ONESH2 0x3C003C00u      // half2(1.0, 1.0)

// ---------------- scratch (device globals; no allocation allowed) ----------------
__device__ __align__(16) fp16 g_qh   [NB * SL * EQ];
__device__ __align__(16) fp16 g_wh   [EQ * 3 * ET];
__device__ __align__(16) fp16 g_qkvh [NB * SL * 3 * ET];
__device__ __align__(16) fp16 g_oh   [NB * SL * ET];
__device__ __align__(16) fp16 g_weffh[NF * ET * EQ];

// ---------------- PTX helpers ----------------
__device__ __forceinline__ uint32_t sptr(const void* p) {
    return (uint32_t)__cvta_generic_to_shared(p);
}
__device__ __forceinline__ void cpasync16(uint32_t s, const void* g) {
    asm volatile("cp.async.cg.shared.global [%0], [%1], 16;\n" :: "r"(s), "l"(g));
}
__device__ __forceinline__ void cpcommit() {
    asm volatile("cp.async.commit_group;\n");
}
template<int N> __device__ __forceinline__ void cpwait() {
    asm volatile("cp.async.wait_group %0;\n" :: "n"(N));
}
__device__ __forceinline__ void ldsm4(uint32_t* r, uint32_t a) {
    asm volatile("ldmatrix.sync.aligned.m8n8.x4.shared.b16 {%0,%1,%2,%3},[%4];\n"
                 : "=r"(r[0]), "=r"(r[1]), "=r"(r[2]), "=r"(r[3]) : "r"(a));
}
__device__ __forceinline__ void ldsm4t(uint32_t* r, uint32_t a) {
    asm volatile("ldmatrix.sync.aligned.m8n8.x4.trans.shared.b16 {%0,%1,%2,%3},[%4];\n"
                 : "=r"(r[0]), "=r"(r[1]), "=r"(r[2]), "=r"(r[3]) : "r"(a));
}
__device__ __forceinline__ void mmah(float* c, const uint32_t* a, uint32_t b0, uint32_t b1) {
    asm volatile("mma.sync.aligned.m16n8k16.row.col.f32.f16.f16.f32 "
                 "{%0,%1,%2,%3},{%4,%5,%6,%7},{%8,%9},{%0,%1,%2,%3};\n"
                 : "+f"(c[0]), "+f"(c[1]), "+f"(c[2]), "+f"(c[3])
                 : "r"(a[0]), "r"(a[1]), "r"(a[2]), "r"(a[3]), "r"(b0), "r"(b1));
}
__device__ __forceinline__ uint32_t cvt2h(float hi, float lo) {
    uint32_t d;
    asm("cvt.rn.f16x2.f32 %0, %1, %2;" : "=r"(d) : "f"(hi), "f"(lo));
    return d;
}
__device__ __forceinline__ uint32_t ex2h2(uint32_t x) {
    uint32_t d;
    asm("ex2.approx.f16x2 %0, %1;" : "=r"(d) : "r"(x));
    return d;
}

// ---------------- split: query + Wqkv -> single fp16 ----------------
#define NQ4 (NB * SL * EQ / 4)
#define NW4 (EQ * 3 * ET / 4)

__global__ void __launch_bounds__(256)
split_kernel(const float* __restrict__ query, const float* __restrict__ Wqkv,
             fp16* __restrict__ qh, fp16* __restrict__ wh)
{
    int i = blockIdx.x * 256 + threadIdx.x;
    if (i < NQ4) {
        float4 v = ((const float4*)query)[i];
        ((__half2*)qh)[2 * i]     = __halves2half2(__float2half_rn(v.x), __float2half_rn(v.y));
        ((__half2*)qh)[2 * i + 1] = __halves2half2(__float2half_rn(v.z), __float2half_rn(v.w));
    } else if (i < NQ4 + NW4) {
        int j = i - NQ4;
        float4 v = ((const float4*)Wqkv)[j];
        ((__half2*)wh)[2 * j]     = __halves2half2(__float2half_rn(v.x), __float2half_rn(v.y));
        ((__half2*)wh)[2 * j + 1] = __halves2half2(__float2half_rn(v.z), __float2half_rn(v.w));
    }
}

// ---------------- fp16 tensor-core GEMM, 128x128 tiles, BK=64, 2 stages ----------
__global__ void __launch_bounds__(256)
mma_gemm(const fp16* __restrict__ Ah_, const fp16* __restrict__ Bh_,
         const float* __restrict__ bias, float* __restrict__ C,
         fp16* __restrict__ Ch, int qscaleCols,
         int M, int N, int K, size_t aB, size_t bB, size_t cB)
{
    constexpr int BHOc = 9216;
    constexpr int GSc  = BHOc + 8704;

    extern __shared__ fp16 sm[];
    int z = blockIdx.z;

    int tid = threadIdx.x, lane = tid & 31, wid = tid >> 5;
    int wm = wid >> 2, wn = wid & 3;
    int m0 = blockIdx.y * 128, n0c = blockIdx.x * 128;
    uint32_t sbase = sptr(sm);

    int chunk = tid & 7, rowa = tid >> 3;
    int ckb = tid & 15, rowb = tid >> 4;

    const fp16* aP = Ah_ + (size_t)(z >> 3) * aB + (size_t)(m0 + rowa) * K + chunk * 8;
    const fp16* bP = Bh_ + (size_t)(z & 7) * bB + (size_t)rowb * N + n0c + ckb * 8;
    const size_t aStep = (size_t)32 * K;
    const size_t bStep = (size_t)16 * N;
    uint32_t sAo = (uint32_t)(rowa * 72 + chunk * 8) * 2;
    uint32_t sBo = (uint32_t)(BHOc + rowb * 136 + ckb * 8) * 2;

    auto loadTile = [&](int buf) {
        uint32_t sb = sbase + buf * GSc * 2;
#pragma unroll
        for (int rep = 0; rep < 4; rep++) {
            cpasync16(sb + sAo + rep * (32 * 72 * 2), aP + rep * aStep);
            cpasync16(sb + sBo + rep * (16 * 136 * 2), bP + rep * bStep);
        }
        cpcommit();
        aP += 64;
        bP += (size_t)64 * N;
    };

    float acc[4][4][4];
#pragma unroll
    for (int i = 0; i < 4; i++)
#pragma unroll
        for (int j = 0; j < 4; j++)
#pragma unroll
            for (int k = 0; k < 4; k++) acc[i][j][k] = 0.f;

    int arow = wm * 64 + (lane & 15);
    int acolsel = (lane >> 4) << 3;
    int krow = (lane & 7) + ((lane >> 4) << 3);
    int bcolw = wn * 32 + ((lane >> 3) & 1) * 8;
    uint32_t aoff = (uint32_t)(arow * 72 + acolsel) * 2;
    uint32_t boff = (uint32_t)(BHOc + krow * 136 + bcolw) * 2;

    int nk = K / 64;
    loadTile(0);
    for (int kt = 0; kt < nk; kt++) {
        if (kt + 1 < nk) { loadTile((kt + 1) & 1); cpwait<1>(); }
        else             { cpwait<0>(); }
        __syncthreads();
        uint32_t aB0 = sbase + (kt & 1) * GSc * 2 + aoff;
        uint32_t bB0 = sbase + (kt & 1) * GSc * 2 + boff;

        uint32_t bcur[2][4];
        ldsm4t(bcur[0], bB0);
        ldsm4t(bcur[1], bB0 + 32);
#pragma unroll
        for (int ks = 0; ks < 4; ks++) {
            uint32_t ah[4][4];
#pragma unroll
            for (int mi = 0; mi < 4; mi++)
                ldsm4(ah[mi], aB0 + ks * 32 + mi * (16 * 72 * 2));
            uint32_t bnxt[2][4];
            if (ks < 3) {
                ldsm4t(bnxt[0], bB0 + (ks + 1) * (16 * 136 * 2));
                ldsm4t(bnxt[1], bB0 + (ks + 1) * (16 * 136 * 2) + 32);
            }
#pragma unroll
            for (int mi = 0; mi < 4; mi++)
#pragma unroll
                for (int nf = 0; nf < 4; nf++) {
                    int g = nf >> 1, s = nf & 1;
                    mmah(acc[mi][nf], ah[mi], bcur[g][s], bcur[g][s + 2]);
                }
            if (ks < 3) {
#pragma unroll
                for (int g = 0; g < 2; g++)
#pragma unroll
                    for (int s = 0; s < 4; s++) bcur[g][s] = bnxt[g][s];
            }
        }
        __syncthreads();
    }

#pragma unroll
    for (int mi = 0; mi < 4; mi++)
#pragma unroll
        for (int nf = 0; nf < 4; nf++) {
            int r = m0 + wm * 64 + mi * 16 + (lane >> 2);
            int c = n0c + wn * 32 + nf * 8 + (lane & 3) * 2;
            float b0 = bias[c], b1 = bias[c + 1];
            float v00 = acc[mi][nf][0] + b0, v01 = acc[mi][nf][1] + b1;
            float v10 = acc[mi][nf][2] + b0, v11 = acc[mi][nf][3] + b1;
            if (qscaleCols && c < qscaleCols) {
                v00 *= QSCALE; v01 *= QSCALE; v10 *= QSCALE; v11 *= QSCALE;
            }
            if (Ch) {
                size_t i0 = (size_t)z * cB + (size_t)r * N + c;
                size_t i1 = i0 + (size_t)8 * N;
                *(__half2*)(Ch + i0) = __halves2half2(__float2half_rn(v00), __float2half_rn(v01));
                *(__half2*)(Ch + i1) = __halves2half2(__float2half_rn(v10), __float2half_rn(v11));
            } else {
                float* Cz = C + (size_t)z * cB;
                *(float2*)(Cz + (size_t)r * N + c) = make_float2(v00, v01);
                *(float2*)(Cz + (size_t)(r + 8) * N + c) = make_float2(v10, v11);
            }
        }
}

// ---------------- powweff device function (runs inside attention launch) ----------
__device__ void powweff_body(float* pw, const float* __restrict__ Xi,
                             const float* __restrict__ Wo, int idx)
{
    float* Mh = pw;
    float* R  = pw + 4352;
    float* RT = pw + 2 * 4352;
    int half = idx & 1;
    int nh = idx >> 1;
    int n = nh >> 3, h = nh & 7;
    int tid = threadIdx.x;
    const float* X = Xi + h * 64 * 64;

#pragma unroll
    for (int t = 0; t < 16; t++) {
        int id2 = tid + t * 256;
        int i = id2 >> 6, j = id2 & 63;
        float v = X[i * 64 + j] - X[j * 64 + i];
        if (i == j) v += 1.f;
        Mh[i * 68 + j] = v;
        R [i * 68 + j] = v;
        RT[j * 68 + i] = v;
    }
    __syncthreads();

    int i0 = (tid >> 4) * 4, j0 = (tid & 15) * 4;
    auto mult = [&](const float* B) {
        float acc[4][4];
#pragma unroll
        for (int a = 0; a < 4; a++)
#pragma unroll
            for (int bq = 0; bq < 4; bq++) acc[a][bq] = 0.f;
#pragma unroll 4
        for (int k = 0; k < 64; k++) {
            float4 av = *(const float4*)&RT[k * 68 + i0];
            float4 bv = *(const float4*)&B[k * 68 + j0];
            float aa[4] = {av.x, av.y, av.z, av.w};
            float bb[4] = {bv.x, bv.y, bv.z, bv.w};
#pragma unroll
            for (int a = 0; a < 4; a++)
#pragma unroll
                for (int bq = 0; bq < 4; bq++)
                    acc[a][bq] = fmaf(aa[a], bb[bq], acc[a][bq]);
        }
        __syncthreads();
#pragma unroll
        for (int a = 0; a < 4; a++)
#pragma unroll
            for (int bq = 0; bq < 4; bq++) {
                R [(i0 + a) * 68 + j0 + bq] = acc[a][bq];
                RT[(j0 + bq) * 68 + i0 + a] = acc[a][bq];
            }
        __syncthreads();
    };

    int e = n + 1;
    if (e > 1) {
        int msb = 31 - __clz(e);
        for (int bpos = msb - 1; bpos >= 0; bpos--) {
            mult(R);
            if ((e >> bpos) & 1) mult(Mh);
        }
    }

    int c = half * 256 + tid;
    const float* WoH = Wo + (size_t)h * 64 * EQ;
    size_t ob = (size_t)n * ET * EQ + (size_t)h * 64 * EQ;
    float acc[4][16];
#pragma unroll
    for (int p = 0; p < 4; p++)
#pragma unroll
        for (int ii = 0; ii < 16; ii++) acc[p][ii] = 0.f;
    for (int j = 0; j < 64; j++) {
        float wv = WoH[j * EQ + c];
        const float* row = &RT[j * 68];
#pragma unroll
        for (int p = 0; p < 4; p++) {
#pragma unroll
            for (int q4 = 0; q4 < 4; q4++) {
                float4 rv = *(const float4*)&row[p * 16 + q4 * 4];
                acc[p][q4 * 4 + 0] = fmaf(rv.x, wv, acc[p][q4 * 4 + 0]);
                acc[p][q4 * 4 + 1] = fmaf(rv.y, wv, acc[p][q4 * 4 + 1]);
                acc[p][q4 * 4 + 2] = fmaf(rv.z, wv, acc[p][q4 * 4 + 2]);
                acc[p][q4 * 4 + 3] = fmaf(rv.w, wv, acc[p][q4 * 4 + 3]);
            }
        }
    }
#pragma unroll
    for (int p = 0; p < 4; p++)
#pragma unroll
        for (int ii = 0; ii < 16; ii++)
            g_weffh[ob + (size_t)(p * 16 + ii) * EQ + c] = __float2half_rn(acc[p][ii]);
}

// ---------------- attention + powweff, one launch ----------------
#define ASTR 72
#define QH_OFF 0
#define KV_OFF 9216
#define KVSTAGE 9216
#define ATTN_SMEM ((9216 + 3 * 9216) * 2)
#define PW_BLOCKS (2 * NF * NH)

__global__ void __launch_bounds__(256, 2)
attn_pow_kernel(const float* __restrict__ Xi, const float* __restrict__ Wo)
{
    extern __shared__ fp16 smb[];
    if (blockIdx.x < PW_BLOCKS) {
        powweff_body((float*)smb, Xi, Wo, blockIdx.x);
        return;
    }
    int ab = blockIdx.x - PW_BLOCKS;
    int qt = 15 - (ab & 15);
    int bh = ab >> 4;
    int b = bh >> 3, h = bh & 7;
    int tid = threadIdx.x, lane = tid & 31, w = tid >> 5;
    int q0 = qt * 128;
    int hoff = h * EH;
    const fp16* qkvh = g_qkvh + (size_t)b * SL * 1536;

    {
        int chunk = tid & 7;
        int row = tid >> 3;
#pragma unroll
        for (int it = 0; it < 4; it++) {
            int r = row + it * 32;
            cpasync16(sptr(smb + QH_OFF + r * ASTR + chunk * 8),
                      qkvh + (size_t)(q0 + r) * 1536 + hoff + chunk * 8);
        }
    }
    auto loadKV = [&](int kt, int stage) {
        int kv0 = kt * 64;
        fp16* base = smb + KV_OFF + stage * KVSTAGE;
        int chunk = tid & 7;
        int row = tid >> 3;
#pragma unroll
        for (int it = 0; it < 4; it++) {
            int arr = it >> 1;
            int r = row + (it & 1) * 32;
            int colbase = (arr == 0) ? (ET + hoff) : (2 * ET + hoff);
            cpasync16(sptr(base + arr * 4608 + r * ASTR + chunk * 8),
                      qkvh + (size_t)(kv0 + r) * 1536 + colbase + chunk * 8);
        }
        cpcommit();
    };

    int kmax = 2 * qt + 1;
    loadKV(0, 0);
    loadKV(1, 1);

    float lacc[4] = {0.f, 0.f, 0.f, 0.f};   // ones-mma row sums (l0=lacc[0], l1=lacc[2])
    float oc[8][4];
#pragma unroll
    for (int i = 0; i < 8; i++)
#pragma unroll
        for (int j = 0; j < 4; j++) oc[i][j] = 0.f;

    int arow = w * 16 + (lane & 15);
    int acolsel = (lane >> 4) << 3;
    int krow = (lane & 7) + ((lane >> 4) << 3);
    int kcolsel = ((lane >> 3) & 1) << 3;
    int vrowbase = krow;

    cpwait<1>();
    __syncthreads();

    uint32_t qf[4][4];
#pragma unroll
    for (int kc = 0; kc < 4; kc++)
        ldsm4(qf[kc], sptr(smb + QH_OFF + arow * ASTR + kc * 16 + acolsel));

    for (int kt = 0; kt <= kmax; kt++) {
        if (kt > 0) {
            cpwait<1>();
            __syncthreads();
        }
        if (kt + 2 <= kmax) loadKV(kt + 2, (kt + 2) % 3);
        else                cpcommit();

        fp16* base = smb + KV_OFF + (kt % 3) * KVSTAGE;
        fp16* KH = base;
        fp16* VH = base + 4608;

        // ---- S = Qh Kh^T, accumulator pre-seeded with -EXP2_OFF ----
        float sc[8][4];
#pragma unroll
        for (int i = 0; i < 8; i++)
#pragma unroll
            for (int j = 0; j < 4; j++) sc[i][j] = -EXP2_OFF;

#pragma unroll
        for (int kc = 0; kc < 4; kc++) {
            int kcol = kc * 16 + kcolsel;
#pragma unroll
            for (int g = 0; g < 4; g++) {
                uint32_t b4h[4];
                ldsm4(b4h, sptr(KH + (g * 16 + krow) * ASTR + kcol));
                mmah(sc[2 * g],     qf[kc], b4h[0], b4h[1]);
                mmah(sc[2 * g + 1], qf[kc], b4h[2], b4h[3]);
            }
        }

        // ---- causal mask (diagonal tiles only) ----
        if (kt >= 2 * qt) {
            int kv0 = kt * 64;
            int r0 = q0 + w * 16 + (lane >> 2);
#pragma unroll
            for (int nf = 0; nf < 8; nf++) {
                int c0 = kv0 + nf * 8 + (lane & 3) * 2;
                if (c0 > r0)     sc[nf][0] = -1e30f;
                if (c0 + 1 > r0) sc[nf][1] = -1e30f;
                if (c0 > r0 + 8)     sc[nf][2] = -1e30f;
                if (c0 + 1 > r0 + 8) sc[nf][3] = -1e30f;
            }
        }

        // ---- P = ex2(S) in fp16x2; l via ones-mma; O += P V ----
#pragma unroll
        for (int kc = 0; kc < 4; kc++) {
            uint32_t pah[4];
#pragma unroll
            for (int half = 0; half < 2; half++) {
                int nf = 2 * kc + half;
                pah[half * 2 + 0] = ex2h2(cvt2h(sc[nf][1], sc[nf][0]));
                pah[half * 2 + 1] = ex2h2(cvt2h(sc[nf][3], sc[nf][2]));
            }
            mmah(lacc, pah, ONESH2, ONESH2);     // row sums (all cols identical)
            int vrow = kc * 16 + vrowbase;
#pragma unroll
            for (int g = 0; g < 4; g++) {
                int vcol = g * 16 + kcolsel;
                uint32_t v4h[4];
                ldsm4t(v4h, sptr(VH + vrow * ASTR + vcol));
                mmah(oc[2 * g],     pah, v4h[0], v4h[2]);
                mmah(oc[2 * g + 1], pah, v4h[1], v4h[3]);
            }
        }
    }

    float inv0 = 1.f / lacc[0], inv1 = 1.f / lacc[2];
    int row0 = q0 + w * 16 + (lane >> 2);
    size_t ob = (size_t)b * SL * ET;
#pragma unroll
    for (int nf = 0; nf < 8; nf++) {
        int col = hoff + nf * 8 + (lane & 3) * 2;
        size_t i0 = ob + (size_t)row0 * ET + col;
        size_t i1 = ob + (size_t)(row0 + 8) * ET + col;
        *(__half2*)(g_oh + i0) = __halves2half2(
            __float2half_rn(oc[nf][0] * inv0), __float2half_rn(oc[nf][1] * inv0));
        *(__half2*)(g_oh + i1) = __halves2half2(
            __float2half_rn(oc[nf][2] * inv1), __float2half_rn(oc[nf][3] * inv1));
    }
}

// ---------------- launch ----------------
extern "C" void kernel_launch(void* const* d_in, const int* in_sizes, int n_in,
                              void* d_out, int out_size)
{
    const float* query = (const float*)d_in[0];
    const float* Wqkv  = (const float*)d_in[3];
    const float* bqkv  = (const float*)d_in[4];
    const float* Wo    = (const float*)d_in[5];
    const float* bo    = (const float*)d_in[6];
    const float* Xi    = (const float*)d_in[7];
    float* out = (float*)d_out;

    fp16 *qh, *wh, *qkvh, *oh, *weh;
    cudaGetSymbolAddress((void**)&qh, g_qh);
    cudaGetSymbolAddress((void**)&wh, g_wh);
    cudaGetSymbolAddress((void**)&qkvh, g_qkvh);
    cudaGetSymbolAddress((void**)&oh, g_oh);
    cudaGetSymbolAddress((void**)&weh, g_weffh);

    constexpr int SM1 = 2 * 17920 * 2;
    cudaFuncSetAttribute(mma_gemm, cudaFuncAttributeMaxDynamicSharedMemorySize, SM1);
    cudaFuncSetAttribute(attn_pow_kernel, cudaFuncAttributeMaxDynamicSharedMemorySize, ATTN_SMEM);

    // 0) fp16 splits (query, Wqkv)
    split_kernel<<<(NQ4 + NW4 + 255) / 256, 256>>>(query, Wqkv, qh, wh);

    // 1) QKV projection -> fp16 qkv, q cols scaled by log2e/8
    dim3 g1(3 * ET / 128, NB * SL / 128, 1);
    mma_gemm<<<g1, 256, SM1>>>(qh, wh, bqkv, nullptr, qkvh, EQ,
                               NB * SL, 3 * ET, EQ, 0, 0, (size_t)0);

    // 2) attention + powweff in one launch
    attn_pow_kernel<<<PW_BLOCKS + 16 * NB * NH, 256, ATTN_SMEM>>>(Xi, Wo);

    // 3) fused forecast+output projection -> fp32 out
    dim3 g2(EQ / 128, SL / 128, NB * NF);
    mma_gemm<<<g2, 256, SM1>>>(oh, weh, bo, out, nullptr, 0,
                               SL, EQ, ET,
                               (size_t)SL * ET, (size_t)ET * EQ, (size_t)SL * EQ);
}